// round 16
// baseline (speedup 1.0000x reference)
#include <cuda_runtime.h>
#include <cuda_fp16.h>
#include <cstdint>
#include <cstddef>

#define NPIX 32768   // B*H*W = 8*64*64
#define CDIM 512
#define KN   1024
#define VC   512
#define HW   4096    // H*W

typedef unsigned long long u64;

// ---------------- scratch (static device globals; no allocation) ----------------
__device__ __half g_xh[(size_t)NPIX * CDIM];     // xn hi (fp16)
__device__ __half g_mh [KN * CDIM];              // mn hi
__device__ __half g_m2h[KN * CDIM];              // mn2 hi
__device__ __half g_sth[(size_t)VC * KN];        // std^T hi
__device__ __half g_ph[(size_t)NPIX * KN];       // prob hi
__device__ float g_esum[KN * CDIM];
__device__ float g_cnt [KN];
__device__ u64   g_arg [NPIX];                   // encoded (score,~idx) argmax
__device__ float g_prob[(size_t)NPIX * KN];      // fp32 score2 fallback buffer

// ============================= PTX helpers =============================
__device__ __forceinline__ uint32_t smem_u32(const void* p) {
    uint32_t a;
    asm("{ .reg .u64 t; cvta.to.shared.u64 t, %1; cvt.u32.u64 %0, t; }" : "=r"(a) : "l"(p));
    return a;
}
__device__ __forceinline__ void bulk_ld(uint32_t sdst, const void* gsrc,
                                        uint32_t bytes, uint32_t mbar) {
    asm volatile("cp.async.bulk.shared::cluster.global.mbarrier::complete_tx::bytes "
                 "[%0], [%1], %2, [%3];"
                 :: "r"(sdst), "l"(gsrc), "r"(bytes), "r"(mbar) : "memory");
}
#define MBAR_INIT(a, n) asm volatile("mbarrier.init.shared.b64 [%0], %1;" :: "r"(a), "r"(n) : "memory")
#define MBAR_EXPECT(a, b) asm volatile("mbarrier.arrive.expect_tx.shared.b64 _, [%0], %1;" :: "r"(a), "r"(b) : "memory")
#define MBAR_WAIT(a, par) do {                                                       \
    uint32_t _m = (a), _p = (par), _d;                                               \
    asm volatile("{\n\t.reg .pred p;\n\t"                                            \
        "mbarrier.try_wait.parity.acquire.cta.shared::cta.b64 p, [%1], %2;\n\t"      \
        "selp.b32 %0, 1, 0, p;\n\t}" : "=r"(_d) : "r"(_m), "r"(_p) : "memory");      \
    if (!_d) {                                                                       \
        asm volatile("{\n\t.reg .pred P1;\n\tWL_%=:\n\t"                             \
            "mbarrier.try_wait.parity.acquire.cta.shared::cta.b64 P1, [%0], %1, 0x989680;\n\t" \
            "@P1 bra.uni WD_%=;\n\tbra.uni WL_%=;\n\tWD_%=:\n\t}"                    \
            :: "r"(_m), "r"(_p) : "memory");                                         \
    }                                                                                \
} while (0)
__device__ __forceinline__ void ldsm4(uint32_t* r, uint32_t addr) {
    asm volatile("ldmatrix.sync.aligned.m8n8.x4.shared.b16 {%0,%1,%2,%3}, [%4];"
                 : "=r"(r[0]), "=r"(r[1]), "=r"(r[2]), "=r"(r[3]) : "r"(addr));
}
__device__ __forceinline__ void mma16816(float* d, const uint32_t* a, uint32_t b0, uint32_t b1) {
    asm volatile("mma.sync.aligned.m16n8k16.row.col.f32.f16.f16.f32 "
                 "{%0,%1,%2,%3}, {%4,%5,%6,%7}, {%8,%9}, {%0,%1,%2,%3};"
                 : "+f"(d[0]), "+f"(d[1]), "+f"(d[2]), "+f"(d[3])
                 : "r"(a[0]), "r"(a[1]), "r"(a[2]), "r"(a[3]), "r"(b0), "r"(b1));
}
__device__ __forceinline__ unsigned fenc(float f) {
    unsigned u = __float_as_uint(f);
    return (u & 0x80000000u) ? ~u : (u | 0x80000000u);
}

// tiles: A 128 rows, B 256 rows; K-chunk = 128 fp16 = 256B data + 16B pad; 2-stage
#define ROWB   272
#define ATILEB (128 * ROWB)         // 34816
#define BTILEB (256 * ROWB)         // 69632
#define STRIDE (ATILEB + BTILEB)    // 104448
#define CHUNK_BYTES ((128 + 256) * 256)          // 98304 per stage
#define SMEM_DYN (2 * STRIDE + 16)  // + 2 mbarriers

// ===== HMMA GEMM: C tile (128 x 256) = A(M,Cd) @ B(Nc,Cd)^T, fp16 in / fp32 acc =====
// 256 threads, 8 warps (2x4), warp tile 64x64; loads via cp.async.bulk + mbarrier
// mode 0: row argmax -> g_arg ; else: store fp32 rows to outp (width outW)
__global__ void __launch_bounds__(256, 1) k_mma(
    const __half* __restrict__ Ah, const __half* __restrict__ Bh,
    int Cd, int outW, int mode, float* __restrict__ outp)
{
    extern __shared__ char smc[];
    const int tid = threadIdx.x, warp = tid >> 5, lane = tid & 31;
    const int wm = warp >> 2, wn = warp & 3;
    const int row0 = blockIdx.y * 128, col0 = blockIdx.x * 256;

    const uint32_t sBase = smem_u32(smc);
    const uint32_t mb0 = sBase + 2 * STRIDE;     // two mbarriers
    const int nCh = Cd >> 7;   // chunks of 128 fp16 cols

    if (tid == 0) { MBAR_INIT(mb0, 1); MBAR_INIT(mb0 + 8, 1); }
    __syncthreads();

    // issue bulk loads for chunk c into stage buf; 384 row-transfers of 256B
    auto loadChunk = [&](int c, int buf) {
        int c0 = c << 7;
        uint32_t base = sBase + buf * STRIDE;
        if (tid == 0) MBAR_EXPECT(mb0 + buf * 8, CHUNK_BYTES);
        __syncwarp(0xFFFFFFFFu);   // harmless; expect ordering not required, kept cheap
        // j = tid (0..255) and tid+256 (<384)
        {
            int j = tid;
            const __half* src = (j < 128)
                ? Ah + (size_t)(row0 + j) * Cd + c0
                : Bh + (size_t)(col0 + (j - 128)) * Cd + c0;
            uint32_t dst = (j < 128)
                ? base + (uint32_t)j * ROWB
                : base + ATILEB + (uint32_t)(j - 128) * ROWB;
            bulk_ld(dst, src, 256, mb0 + buf * 8);
        }
        if (tid < 128) {
            int j = tid + 256;     // B rows 128..255
            const __half* src = Bh + (size_t)(col0 + (j - 128)) * Cd + c0;
            uint32_t dst = base + ATILEB + (uint32_t)(j - 128) * ROWB;
            bulk_ld(dst, src, 256, mb0 + buf * 8);
        }
    };

    float acc[4][8][4];
    #pragma unroll
    for (int i = 0; i < 4; i++)
        #pragma unroll
        for (int j = 0; j < 8; j++)
            #pragma unroll
            for (int q = 0; q < 4; q++) acc[i][j][q] = 0.f;

    loadChunk(0, 0);
    for (int c = 0; c < nCh; c++) {
        int buf = c & 1;
        if (c + 1 < nCh) loadChunk(c + 1, (c + 1) & 1);
        MBAR_WAIT(mb0 + buf * 8, (c >> 1) & 1);

        uint32_t aH = sBase + buf * STRIDE;
        uint32_t bH = aH + ATILEB;
        #pragma unroll
        for (int s = 0; s < 8; s++) {
            uint32_t ah[4][4], bh[4][4];
            #pragma unroll
            for (int mt = 0; mt < 4; mt++) {
                uint32_t off = (uint32_t)(wm * 64 + mt * 16 + (lane & 15)) * ROWB
                             + (lane >> 4) * 16 + s * 32;
                ldsm4(ah[mt], aH + off);
            }
            #pragma unroll
            for (int np = 0; np < 4; np++) {
                uint32_t off = (uint32_t)(wn * 64 + np * 16 + (lane & 15)) * ROWB
                             + (lane >> 4) * 16 + s * 32;
                ldsm4(bh[np], bH + off);
            }
            #pragma unroll
            for (int mt = 0; mt < 4; mt++)
                #pragma unroll
                for (int nt = 0; nt < 8; nt++) {
                    int np = nt >> 1, half = nt & 1;
                    mma16816(acc[mt][nt], ah[mt], bh[np][half], bh[np][half + 2]);
                }
        }
        __syncthreads();   // all consumers done with buf before it is refilled
    }

    // ----------------- epilogue -----------------
    if (mode == 0) {
        #pragma unroll
        for (int mt = 0; mt < 4; mt++) {
            int rg = row0 + wm * 64 + mt * 16 + (lane >> 2);
            u64 bA = 0, bB = 0;
            #pragma unroll
            for (int nt = 0; nt < 8; nt++) {
                unsigned cb = (unsigned)(col0 + wn * 64 + nt * 8 + (lane & 3) * 2);
                u64 e;
                e = ((u64)fenc(acc[mt][nt][0]) << 32) | (unsigned)(~cb);       if (e > bA) bA = e;
                e = ((u64)fenc(acc[mt][nt][1]) << 32) | (unsigned)(~(cb + 1)); if (e > bA) bA = e;
                e = ((u64)fenc(acc[mt][nt][2]) << 32) | (unsigned)(~cb);       if (e > bB) bB = e;
                e = ((u64)fenc(acc[mt][nt][3]) << 32) | (unsigned)(~(cb + 1)); if (e > bB) bB = e;
            }
            #pragma unroll
            for (int off = 1; off <= 2; off <<= 1) {
                u64 oA = __shfl_xor_sync(~0u, bA, off);
                u64 oB = __shfl_xor_sync(~0u, bB, off);
                if (oA > bA) bA = oA;
                if (oB > bB) bB = oB;
            }
            if ((lane & 3) == 0) {
                atomicMax(&g_arg[rg], bA);
                atomicMax(&g_arg[rg + 8], bB);
            }
        }
    } else {
        #pragma unroll
        for (int mt = 0; mt < 4; mt++) {
            int rg = row0 + wm * 64 + mt * 16 + (lane >> 2);
            #pragma unroll
            for (int nt = 0; nt < 8; nt++) {
                int cg = col0 + wn * 64 + nt * 8 + (lane & 3) * 2;
                float2 lo = {acc[mt][nt][0], acc[mt][nt][1]};
                float2 hi = {acc[mt][nt][2], acc[mt][nt][3]};
                *(float2*)(outp + (size_t)rg * outW + cg)       = lo;
                *(float2*)(outp + (size_t)(rg + 8) * outW + cg) = hi;
            }
        }
    }
}

// ---------------- normalize codebook rows -> fp16 hi ----------------
__global__ __launch_bounds__(128) void k_norm_m(const float* __restrict__ m,
                                                __half* __restrict__ dh) {
    int k = blockIdx.x, tid = threadIdx.x;
    float4 v = ((const float4*)(m + (size_t)k * CDIM))[tid];
    float ss = v.x*v.x + v.y*v.y + v.z*v.z + v.w*v.w;
    #pragma unroll
    for (int o = 16; o; o >>= 1) ss += __shfl_xor_sync(~0u, ss, o);
    __shared__ float sred[4]; __shared__ float sinv;
    if ((tid & 31) == 0) sred[tid >> 5] = ss;
    __syncthreads();
    if (tid == 0) sinv = 1.f / fmaxf(sqrtf(sred[0]+sred[1]+sred[2]+sred[3]), 1e-12f);
    __syncthreads();
    float inv = sinv;
    float o4[4] = {v.x*inv, v.y*inv, v.z*inv, v.w*inv};
    size_t base = (size_t)k * CDIM + tid * 4;
    #pragma unroll
    for (int j = 0; j < 4; j++) dh[base + j] = __float2half_rn(o4[j]);
}

// ---------------- EMA update + normalize -> fp16 hi ----------------
__global__ __launch_bounds__(128) void k_update_m(const float* __restrict__ m) {
    int k = blockIdx.x, tid = threadIdx.x;
    float w = 0.001f / (g_cnt[k] + 1e-6f);
    float4 mv = ((const float4*)(m      + (size_t)k * CDIM))[tid];
    float4 ev = ((const float4*)(g_esum + (size_t)k * CDIM))[tid];
    float nv[4] = { mv.x*0.999f + ev.x*w, mv.y*0.999f + ev.y*w,
                    mv.z*0.999f + ev.z*w, mv.w*0.999f + ev.w*w };
    float ss = nv[0]*nv[0] + nv[1]*nv[1] + nv[2]*nv[2] + nv[3]*nv[3];
    #pragma unroll
    for (int o = 16; o; o >>= 1) ss += __shfl_xor_sync(~0u, ss, o);
    __shared__ float sred[4]; __shared__ float sinv;
    if ((tid & 31) == 0) sred[tid >> 5] = ss;
    __syncthreads();
    if (tid == 0) sinv = 1.f / fmaxf(sqrtf(sred[0]+sred[1]+sred[2]+sred[3]), 1e-12f);
    __syncthreads();
    float inv = sinv;
    size_t base = (size_t)k * CDIM + tid * 4;
    #pragma unroll
    for (int j = 0; j < 4; j++)
        g_m2h[base + j] = __float2half_rn(nv[j] * inv);
}

// ---------------- transpose std (K,V)->(V,K), fp16 hi ----------------
__global__ void k_tstd(const float* __restrict__ s) {
    __shared__ float t[32][33];
    int v0 = blockIdx.x * 32, k0 = blockIdx.y * 32;
    int tx = threadIdx.x, ty = threadIdx.y;  // 32 x 8
    #pragma unroll
    for (int i = 0; i < 4; i++)
        t[ty + 8*i][tx] = s[(size_t)(k0 + ty + 8*i) * VC + v0 + tx];
    __syncthreads();
    #pragma unroll
    for (int i = 0; i < 4; i++) {
        float v = t[tx][ty + 8*i];
        g_sth[(size_t)(v0 + ty + 8*i) * KN + k0 + tx] = __float2half_rn(v);
    }
}

// ---------------- transpose (b,c,h,w)->(n,c), normalize rows -> fp16 hi ----------------
__global__ __launch_bounds__(256) void k_prep_x(const float* __restrict__ x) {
    __shared__ float s[CDIM][17];
    __shared__ float rsum[16][17];
    int bid = blockIdx.x;             // 0..2047
    int b   = bid >> 8;               // / 256
    int hw0 = (bid & 255) << 4;       // * 16
    int tx = threadIdx.x & 15, ty = threadIdx.x >> 4;
    const float* xb = x + (size_t)b * CDIM * HW + hw0;
    float ss = 0.f;
    for (int c = ty; c < CDIM; c += 16) {
        float v = xb[(size_t)c * HW + tx];
        s[c][tx] = v;
        ss += v * v;
    }
    rsum[ty][tx] = ss;
    __syncthreads();
    if (ty < 8) rsum[ty][tx] += rsum[ty + 8][tx];
    __syncthreads();
    if (ty < 4) rsum[ty][tx] += rsum[ty + 4][tx];
    __syncthreads();
    if (ty < 2) rsum[ty][tx] += rsum[ty + 2][tx];
    __syncthreads();
    if (ty == 0) {
        float norm = fmaxf(sqrtf(rsum[0][tx] + rsum[1][tx]), 1e-12f);
        rsum[0][tx] = 1.f / norm;
    }
    __syncthreads();
    int warp = threadIdx.x >> 5, lane = threadIdx.x & 31;
    #pragma unroll
    for (int q = 0; q < 2; q++) {
        int p = warp * 2 + q;
        float inv = rsum[0][p];
        size_t rbase = (size_t)(b * HW + hw0 + p) * CDIM;
        for (int c = lane; c < CDIM; c += 32)
            g_xh[rbase + c] = __float2half_rn(s[c][p] * inv);
    }
}

// ---------------- zero segment buffers + argmax buffer ----------------
__global__ void k_zero() {
    int i = blockIdx.x * blockDim.x + threadIdx.x;
    if (i < KN * CDIM) g_esum[i] = 0.f;
    if (i < KN)        g_cnt[i]  = 0.f;
    if (i < NPIX)      g_arg[i]  = 0ull;
}

// ---------------- scatter: raw x -> esum via vectorized red; counts inline ----------------
__global__ __launch_bounds__(256) void k_scatter(const float* __restrict__ x) {
    int t = blockIdx.x * blockDim.x + threadIdx.x;   // [0, NPIX*128)
    int n  = t & (NPIX - 1);
    int cq = t >> 15;            // 0..127
    int c0 = cq << 2;
    int idx = (int)(~(unsigned)(g_arg[n] & 0xFFFFFFFFull));
    int b = n >> 12, hw = n & (HW - 1);
    const float* xb = x + (size_t)b * CDIM * HW + (size_t)c0 * HW + hw;
    float v0 = xb[0];
    float v1 = xb[HW];
    float v2 = xb[2 * HW];
    float v3 = xb[3 * HW];
    float* dst = g_esum + (size_t)idx * CDIM + c0;
    asm volatile("red.global.add.v4.f32 [%0], {%1,%2,%3,%4};"
                 :: "l"(dst), "f"(v0), "f"(v1), "f"(v2), "f"(v3) : "memory");
    if (cq == 0) atomicAdd(&g_cnt[idx], 1.f);
}

// ---------------- softmax rows of score2 -> fp16 prob (hi only) ----------------
__global__ __launch_bounds__(256) void k_softmax(const float* __restrict__ s2) {
    int n = blockIdx.x, tid = threadIdx.x;
    float4 v = ((const float4*)(s2 + (size_t)n * KN))[tid];
    float mx = fmaxf(fmaxf(v.x, v.y), fmaxf(v.z, v.w));
    #pragma unroll
    for (int o = 16; o; o >>= 1) mx = fmaxf(mx, __shfl_xor_sync(~0u, mx, o));
    __shared__ float sm[8];
    if ((tid & 31) == 0) sm[tid >> 5] = mx;
    __syncthreads();
    if (tid < 32) {
        float t = (tid < 8) ? sm[tid] : -3.4e38f;
        #pragma unroll
        for (int o = 4; o; o >>= 1) t = fmaxf(t, __shfl_xor_sync(~0u, t, o));
        if (tid == 0) sm[0] = t;
    }
    __syncthreads();
    float M = sm[0];
    float e0 = __expf(v.x - M), e1 = __expf(v.y - M);
    float e2 = __expf(v.z - M), e3 = __expf(v.w - M);
    float ssum = e0 + e1 + e2 + e3;
    #pragma unroll
    for (int o = 16; o; o >>= 1) ssum += __shfl_xor_sync(~0u, ssum, o);
    __shared__ float sq[8];
    if ((tid & 31) == 0) sq[tid >> 5] = ssum;
    __syncthreads();
    if (tid < 32) {
        float t = (tid < 8) ? sq[tid] : 0.f;
        #pragma unroll
        for (int o = 4; o; o >>= 1) t += __shfl_xor_sync(~0u, t, o);
        if (tid == 0) sq[0] = t;
    }
    __syncthreads();
    float inv = 1.f / sq[0];
    float p[4] = {e0 * inv, e1 * inv, e2 * inv, e3 * inv};
    size_t base = (size_t)n * KN + tid * 4;
    #pragma unroll
    for (int j = 0; j < 4; j++)
        g_ph[base + j] = __float2half_rn(p[j]);
}

// ---------------- launch ----------------
extern "C" void kernel_launch(void* const* d_in, const int* in_sizes, int n_in,
                              void* d_out, int out_size) {
    const float* x    = (const float*)d_in[0];   // (8,512,64,64)
    const float* m    = (const float*)d_in[1];   // (1024,512)
    const float* stdw = (const float*)d_in[2];   // (1024,512)
    float* out = (float*)d_out;

    __half *p_xh, *p_mh, *p_m2h, *p_sth, *p_ph;
    float* p_prob;
    cudaGetSymbolAddress((void**)&p_xh,  g_xh);
    cudaGetSymbolAddress((void**)&p_mh,  g_mh);
    cudaGetSymbolAddress((void**)&p_m2h, g_m2h);
    cudaGetSymbolAddress((void**)&p_sth, g_sth);
    cudaGetSymbolAddress((void**)&p_ph,  g_ph);
    cudaGetSymbolAddress((void**)&p_prob, g_prob);

    cudaFuncSetAttribute(k_mma, cudaFuncAttributeMaxDynamicSharedMemorySize, SMEM_DYN);

    const long long OUT1 = (long long)NPIX * VC;
    const long long S2SZ = (long long)NPIX * KN;
    float* s2 = ((long long)out_size >= OUT1 + S2SZ) ? (out + OUT1) : p_prob;

    k_norm_m <<<KN, 128>>>(m, p_mh);
    k_prep_x <<<2048, 256>>>(x);
    k_zero   <<<(KN * CDIM + 255) / 256, 256>>>();
    // GEMM1: score1 + argmax; grid = (col tiles, row tiles)
    k_mma<<<dim3(KN / 256, NPIX / 128), 256, SMEM_DYN>>>(p_xh, p_mh,
                                                         CDIM, KN, 0, nullptr);
    k_scatter<<<(NPIX * 128) / 256, 256>>>(x);
    k_update_m<<<KN, 128>>>(m);
    k_tstd   <<<dim3(VC / 32, KN / 32), dim3(32, 8)>>>(stdw);
    // GEMM2: score2 (1-pass fp16, fp32 acc)
    k_mma<<<dim3(KN / 256, NPIX / 128), 256, SMEM_DYN>>>(p_xh, p_m2h,
                                                         CDIM, KN, 1, s2);
    k_softmax<<<NPIX, 256>>>(s2);
    // GEMM3: out = prob @ std (operands prob(N,K), std^T(V,K))
    k_mma<<<dim3(VC / 256, NPIX / 128), 256, SMEM_DYN>>>(p_ph, p_sth,
                                                         KN, VC, 2, out);
}

// round 17
// speedup vs baseline: 1.1662x; 1.1662x over previous
#include <cuda_runtime.h>
#include <cuda_fp16.h>
#include <cstdint>
#include <cstddef>

#define NPIX 32768   // B*H*W = 8*64*64
#define CDIM 512
#define KN   1024
#define VC   512
#define HW   4096    // H*W

typedef unsigned long long u64;

// ---------------- scratch (static device globals; no allocation) ----------------
__device__ __half g_xh[(size_t)NPIX * CDIM];     // xn hi (fp16)
__device__ __half g_mh [KN * CDIM];              // mn hi
__device__ __half g_m2h[KN * CDIM];              // mn2 hi
__device__ __half g_sth[(size_t)VC * KN];        // std^T hi
__device__ __half g_ph[(size_t)NPIX * KN];       // prob hi
__device__ float g_esum[KN * CDIM];
__device__ float g_cnt [KN];
__device__ u64   g_arg [NPIX];                   // encoded (score,~idx) argmax
__device__ float g_prob[(size_t)NPIX * KN];      // fp32 score2 fallback buffer

// ============================= PTX helpers (portable, sm_80+) =============================
__device__ __forceinline__ uint32_t smem_u32(const void* p) {
    uint32_t a;
    asm("{ .reg .u64 t; cvta.to.shared.u64 t, %1; cvt.u32.u64 %0, t; }" : "=r"(a) : "l"(p));
    return a;
}
__device__ __forceinline__ void cp16(uint32_t saddr, const void* gaddr) {
    asm volatile("cp.async.cg.shared.global [%0], [%1], 16;" :: "r"(saddr), "l"(gaddr));
}
__device__ __forceinline__ void cp_commit() {
    asm volatile("cp.async.commit_group;" ::: "memory");
}
template <int N>
__device__ __forceinline__ void cp_wait() {
    asm volatile("cp.async.wait_group %0;" :: "n"(N) : "memory");
}
__device__ __forceinline__ void ldsm4(uint32_t* r, uint32_t addr) {
    asm volatile("ldmatrix.sync.aligned.m8n8.x4.shared.b16 {%0,%1,%2,%3}, [%4];"
                 : "=r"(r[0]), "=r"(r[1]), "=r"(r[2]), "=r"(r[3]) : "r"(addr));
}
__device__ __forceinline__ void mma16816(float* d, const uint32_t* a, uint32_t b0, uint32_t b1) {
    asm volatile("mma.sync.aligned.m16n8k16.row.col.f32.f16.f16.f32 "
                 "{%0,%1,%2,%3}, {%4,%5,%6,%7}, {%8,%9}, {%0,%1,%2,%3};"
                 : "+f"(d[0]), "+f"(d[1]), "+f"(d[2]), "+f"(d[3])
                 : "r"(a[0]), "r"(a[1]), "r"(a[2]), "r"(a[3]), "r"(b0), "r"(b1));
}
__device__ __forceinline__ unsigned fenc(float f) {
    unsigned u = __float_as_uint(f);
    return (u & 0x80000000u) ? ~u : (u | 0x80000000u);
}

// tiles: A 128 rows, B 256 rows; K-chunk = 128 fp16 = 256B/row, XOR-swizzled units; 2-stage
// swizzle: 16B unit u of row r stored at unit (u ^ (r & 7)) -> 8-row ldmatrix tiles are
// conflict-free (8 distinct 128B phases per tile).
#define ROWB   256
#define ATILEB (128 * ROWB)         // 32768
#define BTILEB (256 * ROWB)         // 65536
#define STRIDE (ATILEB + BTILEB)    // 98304
#define SMEM_DYN (2 * STRIDE)       // 196608

__device__ __forceinline__ uint32_t swz(int r, int u) {
    return (uint32_t)r * ROWB + (uint32_t)((u ^ (r & 7)) << 4);
}

// ===== HMMA GEMM: C tile (128 x 256) = A(M,Cd) @ B(Nc,Cd)^T, fp16 1-pass, warp 64x64 =====
// mode 0: row argmax -> g_arg ; else: store fp32 rows to outp (width outW)
__global__ void __launch_bounds__(256, 1) k_mma(
    const __half* __restrict__ Ah, const __half* __restrict__ Bh,
    int Cd, int outW, int mode, float* __restrict__ outp)
{
    extern __shared__ char smc[];
    const int tid = threadIdx.x, warp = tid >> 5, lane = tid & 31;
    const int wm = warp >> 2, wn = warp & 3;     // 2 x 4 warp grid, warp tile 64x64
    const int row0 = blockIdx.y * 128, col0 = blockIdx.x * 256;

    const uint32_t sBase = smem_u32(smc);
    const int nCh = Cd >> 7;   // chunks of 128 fp16 cols

    auto loadChunk = [&](int c, int buf) {
        int c0 = c << 7;
        uint32_t base = sBase + buf * STRIDE;
        #pragma unroll
        for (int q = 0; q < 8; q++) {            // A: 128 rows x 16 units
            int u = tid + q * 256;
            int r = u >> 4, uo = u & 15;
            cp16(base + swz(r, uo), Ah + (size_t)(row0 + r) * Cd + c0 + uo * 8);
        }
        #pragma unroll
        for (int q = 0; q < 16; q++) {           // B: 256 rows x 16 units
            int u = tid + q * 256;
            int r = u >> 4, uo = u & 15;
            cp16(base + ATILEB + swz(r, uo),
                 Bh + (size_t)(col0 + r) * Cd + c0 + uo * 8);
        }
        cp_commit();
    };

    float acc[4][8][4];
    #pragma unroll
    for (int i = 0; i < 4; i++)
        #pragma unroll
        for (int j = 0; j < 8; j++)
            #pragma unroll
            for (int q = 0; q < 4; q++) acc[i][j][q] = 0.f;

    loadChunk(0, 0);
    for (int c = 0; c < nCh; c++) {
        int buf = c & 1;
        if (c + 1 < nCh) { loadChunk(c + 1, (c + 1) & 1); cp_wait<1>(); }
        else             { cp_wait<0>(); }
        __syncthreads();

        uint32_t aH = sBase + buf * STRIDE;
        uint32_t bH = aH + ATILEB;
        #pragma unroll
        for (int s = 0; s < 8; s++) {
            uint32_t ah[4][4], bh[4][4];
            int un = 2 * s + (lane >> 4);        // 16B unit index for this lane
            #pragma unroll
            for (int mt = 0; mt < 4; mt++) {
                int r = wm * 64 + mt * 16 + (lane & 15);
                ldsm4(ah[mt], aH + swz(r, un));
            }
            #pragma unroll
            for (int np = 0; np < 4; np++) {
                int r = wn * 64 + np * 16 + (lane & 15);
                ldsm4(bh[np], bH + swz(r, un));
            }
            #pragma unroll
            for (int mt = 0; mt < 4; mt++)
                #pragma unroll
                for (int nt = 0; nt < 8; nt++) {
                    int np = nt >> 1, half = nt & 1;
                    mma16816(acc[mt][nt], ah[mt], bh[np][half], bh[np][half + 2]);
                }
        }
        __syncthreads();
    }

    // ----------------- epilogue -----------------
    if (mode == 0) {
        #pragma unroll
        for (int mt = 0; mt < 4; mt++) {
            int rg = row0 + wm * 64 + mt * 16 + (lane >> 2);
            u64 bA = 0, bB = 0;
            #pragma unroll
            for (int nt = 0; nt < 8; nt++) {
                unsigned cb = (unsigned)(col0 + wn * 64 + nt * 8 + (lane & 3) * 2);
                u64 e;
                e = ((u64)fenc(acc[mt][nt][0]) << 32) | (unsigned)(~cb);       if (e > bA) bA = e;
                e = ((u64)fenc(acc[mt][nt][1]) << 32) | (unsigned)(~(cb + 1)); if (e > bA) bA = e;
                e = ((u64)fenc(acc[mt][nt][2]) << 32) | (unsigned)(~cb);       if (e > bB) bB = e;
                e = ((u64)fenc(acc[mt][nt][3]) << 32) | (unsigned)(~(cb + 1)); if (e > bB) bB = e;
            }
            #pragma unroll
            for (int off = 1; off <= 2; off <<= 1) {
                u64 oA = __shfl_xor_sync(~0u, bA, off);
                u64 oB = __shfl_xor_sync(~0u, bB, off);
                if (oA > bA) bA = oA;
                if (oB > bB) bB = oB;
            }
            if ((lane & 3) == 0) {
                atomicMax(&g_arg[rg], bA);
                atomicMax(&g_arg[rg + 8], bB);
            }
        }
    } else {
        #pragma unroll
        for (int mt = 0; mt < 4; mt++) {
            int rg = row0 + wm * 64 + mt * 16 + (lane >> 2);
            #pragma unroll
            for (int nt = 0; nt < 8; nt++) {
                int cg = col0 + wn * 64 + nt * 8 + (lane & 3) * 2;
                float2 lo = {acc[mt][nt][0], acc[mt][nt][1]};
                float2 hi = {acc[mt][nt][2], acc[mt][nt][3]};
                *(float2*)(outp + (size_t)rg * outW + cg)       = lo;
                *(float2*)(outp + (size_t)(rg + 8) * outW + cg) = hi;
            }
        }
    }
}

// ---------------- normalize codebook rows -> fp16 hi ----------------
__global__ __launch_bounds__(128) void k_norm_m(const float* __restrict__ m,
                                                __half* __restrict__ dh) {
    int k = blockIdx.x, tid = threadIdx.x;
    float4 v = ((const float4*)(m + (size_t)k * CDIM))[tid];
    float ss = v.x*v.x + v.y*v.y + v.z*v.z + v.w*v.w;
    #pragma unroll
    for (int o = 16; o; o >>= 1) ss += __shfl_xor_sync(~0u, ss, o);
    __shared__ float sred[4]; __shared__ float sinv;
    if ((tid & 31) == 0) sred[tid >> 5] = ss;
    __syncthreads();
    if (tid == 0) sinv = 1.f / fmaxf(sqrtf(sred[0]+sred[1]+sred[2]+sred[3]), 1e-12f);
    __syncthreads();
    float inv = sinv;
    float o4[4] = {v.x*inv, v.y*inv, v.z*inv, v.w*inv};
    size_t base = (size_t)k * CDIM + tid * 4;
    #pragma unroll
    for (int j = 0; j < 4; j++) dh[base + j] = __float2half_rn(o4[j]);
}

// ---------------- EMA update + normalize -> fp16 hi ----------------
__global__ __launch_bounds__(128) void k_update_m(const float* __restrict__ m) {
    int k = blockIdx.x, tid = threadIdx.x;
    float w = 0.001f / (g_cnt[k] + 1e-6f);
    float4 mv = ((const float4*)(m      + (size_t)k * CDIM))[tid];
    float4 ev = ((const float4*)(g_esum + (size_t)k * CDIM))[tid];
    float nv[4] = { mv.x*0.999f + ev.x*w, mv.y*0.999f + ev.y*w,
                    mv.z*0.999f + ev.z*w, mv.w*0.999f + ev.w*w };
    float ss = nv[0]*nv[0] + nv[1]*nv[1] + nv[2]*nv[2] + nv[3]*nv[3];
    #pragma unroll
    for (int o = 16; o; o >>= 1) ss += __shfl_xor_sync(~0u, ss, o);
    __shared__ float sred[4]; __shared__ float sinv;
    if ((tid & 31) == 0) sred[tid >> 5] = ss;
    __syncthreads();
    if (tid == 0) sinv = 1.f / fmaxf(sqrtf(sred[0]+sred[1]+sred[2]+sred[3]), 1e-12f);
    __syncthreads();
    float inv = sinv;
    size_t base = (size_t)k * CDIM + tid * 4;
    #pragma unroll
    for (int j = 0; j < 4; j++)
        g_m2h[base + j] = __float2half_rn(nv[j] * inv);
}

// ---------------- transpose std (K,V)->(V,K), fp16 hi ----------------
__global__ void k_tstd(const float* __restrict__ s) {
    __shared__ float t[32][33];
    int v0 = blockIdx.x * 32, k0 = blockIdx.y * 32;
    int tx = threadIdx.x, ty = threadIdx.y;  // 32 x 8
    #pragma unroll
    for (int i = 0; i < 4; i++)
        t[ty + 8*i][tx] = s[(size_t)(k0 + ty + 8*i) * VC + v0 + tx];
    __syncthreads();
    #pragma unroll
    for (int i = 0; i < 4; i++) {
        float v = t[tx][ty + 8*i];
        g_sth[(size_t)(v0 + ty + 8*i) * KN + k0 + tx] = __float2half_rn(v);
    }
}

// ---------------- transpose (b,c,h,w)->(n,c), normalize rows -> fp16 hi ----------------
__global__ __launch_bounds__(256) void k_prep_x(const float* __restrict__ x) {
    __shared__ float s[CDIM][17];
    __shared__ float rsum[16][17];
    int bid = blockIdx.x;             // 0..2047
    int b   = bid >> 8;               // / 256
    int hw0 = (bid & 255) << 4;       // * 16
    int tx = threadIdx.x & 15, ty = threadIdx.x >> 4;
    const float* xb = x + (size_t)b * CDIM * HW + hw0;
    float ss = 0.f;
    for (int c = ty; c < CDIM; c += 16) {
        float v = xb[(size_t)c * HW + tx];
        s[c][tx] = v;
        ss += v * v;
    }
    rsum[ty][tx] = ss;
    __syncthreads();
    if (ty < 8) rsum[ty][tx] += rsum[ty + 8][tx];
    __syncthreads();
    if (ty < 4) rsum[ty][tx] += rsum[ty + 4][tx];
    __syncthreads();
    if (ty < 2) rsum[ty][tx] += rsum[ty + 2][tx];
    __syncthreads();
    if (ty == 0) {
        float norm = fmaxf(sqrtf(rsum[0][tx] + rsum[1][tx]), 1e-12f);
        rsum[0][tx] = 1.f / norm;
    }
    __syncthreads();
    int warp = threadIdx.x >> 5, lane = threadIdx.x & 31;
    #pragma unroll
    for (int q = 0; q < 2; q++) {
        int p = warp * 2 + q;
        float inv = rsum[0][p];
        size_t rbase = (size_t)(b * HW + hw0 + p) * CDIM;
        for (int c = lane; c < CDIM; c += 32)
            g_xh[rbase + c] = __float2half_rn(s[c][p] * inv);
    }
}

// ---------------- zero segment buffers + argmax buffer ----------------
__global__ void k_zero() {
    int i = blockIdx.x * blockDim.x + threadIdx.x;
    if (i < KN * CDIM) g_esum[i] = 0.f;
    if (i < KN)        g_cnt[i]  = 0.f;
    if (i < NPIX)      g_arg[i]  = 0ull;
}

// ---------------- scatter: raw x -> esum via vectorized red; counts inline ----------------
__global__ __launch_bounds__(256) void k_scatter(const float* __restrict__ x) {
    int t = blockIdx.x * blockDim.x + threadIdx.x;   // [0, NPIX*128)
    int n  = t & (NPIX - 1);
    int cq = t >> 15;            // 0..127
    int c0 = cq << 2;
    int idx = (int)(~(unsigned)(g_arg[n] & 0xFFFFFFFFull));
    int b = n >> 12, hw = n & (HW - 1);
    const float* xb = x + (size_t)b * CDIM * HW + (size_t)c0 * HW + hw;
    float v0 = xb[0];
    float v1 = xb[HW];
    float v2 = xb[2 * HW];
    float v3 = xb[3 * HW];
    float* dst = g_esum + (size_t)idx * CDIM + c0;
    asm volatile("red.global.add.v4.f32 [%0], {%1,%2,%3,%4};"
                 :: "l"(dst), "f"(v0), "f"(v1), "f"(v2), "f"(v3) : "memory");
    if (cq == 0) atomicAdd(&g_cnt[idx], 1.f);
}

// ---------------- softmax rows of score2 -> fp16 prob (hi only) ----------------
__global__ __launch_bounds__(256) void k_softmax(const float* __restrict__ s2) {
    int n = blockIdx.x, tid = threadIdx.x;
    float4 v = ((const float4*)(s2 + (size_t)n * KN))[tid];
    float mx = fmaxf(fmaxf(v.x, v.y), fmaxf(v.z, v.w));
    #pragma unroll
    for (int o = 16; o; o >>= 1) mx = fmaxf(mx, __shfl_xor_sync(~0u, mx, o));
    __shared__ float sm[8];
    if ((tid & 31) == 0) sm[tid >> 5] = mx;
    __syncthreads();
    if (tid < 32) {
        float t = (tid < 8) ? sm[tid] : -3.4e38f;
        #pragma unroll
        for (int o = 4; o; o >>= 1) t = fmaxf(t, __shfl_xor_sync(~0u, t, o));
        if (tid == 0) sm[0] = t;
    }
    __syncthreads();
    float M = sm[0];
    float e0 = __expf(v.x - M), e1 = __expf(v.y - M);
    float e2 = __expf(v.z - M), e3 = __expf(v.w - M);
    float ssum = e0 + e1 + e2 + e3;
    #pragma unroll
    for (int o = 16; o; o >>= 1) ssum += __shfl_xor_sync(~0u, ssum, o);
    __shared__ float sq[8];
    if ((tid & 31) == 0) sq[tid >> 5] = ssum;
    __syncthreads();
    if (tid < 32) {
        float t = (tid < 8) ? sq[tid] : 0.f;
        #pragma unroll
        for (int o = 4; o; o >>= 1) t += __shfl_xor_sync(~0u, t, o);
        if (tid == 0) sq[0] = t;
    }
    __syncthreads();
    float inv = 1.f / sq[0];
    float p[4] = {e0 * inv, e1 * inv, e2 * inv, e3 * inv};
    size_t base = (size_t)n * KN + tid * 4;
    #pragma unroll
    for (int j = 0; j < 4; j++)
        g_ph[base + j] = __float2half_rn(p[j]);
}

// ---------------- launch ----------------
extern "C" void kernel_launch(void* const* d_in, const int* in_sizes, int n_in,
                              void* d_out, int out_size) {
    const float* x    = (const float*)d_in[0];   // (8,512,64,64)
    const float* m    = (const float*)d_in[1];   // (1024,512)
    const float* stdw = (const float*)d_in[2];   // (1024,512)
    float* out = (float*)d_out;

    __half *p_xh, *p_mh, *p_m2h, *p_sth, *p_ph;
    float* p_prob;
    cudaGetSymbolAddress((void**)&p_xh,  g_xh);
    cudaGetSymbolAddress((void**)&p_mh,  g_mh);
    cudaGetSymbolAddress((void**)&p_m2h, g_m2h);
    cudaGetSymbolAddress((void**)&p_sth, g_sth);
    cudaGetSymbolAddress((void**)&p_ph,  g_ph);
    cudaGetSymbolAddress((void**)&p_prob, g_prob);

    cudaFuncSetAttribute(k_mma, cudaFuncAttributeMaxDynamicSharedMemorySize, SMEM_DYN);

    const long long OUT1 = (long long)NPIX * VC;
    const long long S2SZ = (long long)NPIX * KN;
    float* s2 = ((long long)out_size >= OUT1 + S2SZ) ? (out + OUT1) : p_prob;

    k_norm_m <<<KN, 128>>>(m, p_mh);
    k_prep_x <<<2048, 256>>>(x);
    k_zero   <<<(KN * CDIM + 255) / 256, 256>>>();
    // GEMM1: score1 + argmax; grid = (col tiles, row tiles)
    k_mma<<<dim3(KN / 256, NPIX / 128), 256, SMEM_DYN>>>(p_xh, p_mh,
                                                         CDIM, KN, 0, nullptr);
    k_scatter<<<(NPIX * 128) / 256, 256>>>(x);
    k_update_m<<<KN, 128>>>(m);
    k_tstd   <<<dim3(VC / 32, KN / 32), dim3(32, 8)>>>(stdw);
    // GEMM2: score2 (1-pass fp16, fp32 acc)
    k_mma<<<dim3(KN / 256, NPIX / 128), 256, SMEM_DYN>>>(p_xh, p_m2h,
                                                         CDIM, KN, 1, s2);
    k_softmax<<<NPIX, 256>>>(s2);
    // GEMM3: out = prob @ std (operands prob(N,K), std^T(V,K))
    k_mma<<<dim3(VC / 256, NPIX / 128), 256, SMEM_DYN>>>(p_ph, p_sth,
                                                         KN, VC, 2, out);
}